// round 2
// baseline (speedup 1.0000x reference)
#include <cuda_runtime.h>
#include <math.h>

#define BB 8
#define CC 256
#define HH 224
#define WW 224
#define CELLS 16
#define KH 56
#define HW (HH*WW)
#define HW4 (HW/4)
#define NUM_LEVELS 3

// scratch (no allocations allowed)
__device__ float  g_coarse[BB*CC*CELLS];   // [b][c][cell]
__device__ float  g_mask[BB*CELLS];
__device__ float4 g_fmask4[BB*HW4];        // per-batch upsampled mask, 1.6MB

// ---------------------------------------------------------------------------
// Kernel 1: grid max pool. One block per (b, c, gy): a contiguous 56x224 slab.
// ---------------------------------------------------------------------------
__global__ void k_pool(const float* __restrict__ x) {
    int bid = blockIdx.x;             // b*1024 + c*4 + gy
    int gy = bid & 3;
    int c  = (bid >> 2) & 255;
    int b  = bid >> 10;
    const float4* src = (const float4*)(x + ((size_t)(b*CC + c)*HH + gy*KH)*WW);

    float lm0 = -3.402823466e38f, lm1 = lm0, lm2 = lm0, lm3 = lm0;
    // slab = 56 rows * 56 float4 = 3136 contiguous float4
    #pragma unroll 4
    for (int i = threadIdx.x; i < 56*56; i += 256) {
        float4 v = src[i];
        float m = fmaxf(fmaxf(v.x, v.y), fmaxf(v.z, v.w));
        int gx = (i % 56) / 14;       // 14 float4 = 56 floats per cell
        if (gx == 0)      lm0 = fmaxf(lm0, m);
        else if (gx == 1) lm1 = fmaxf(lm1, m);
        else if (gx == 2) lm2 = fmaxf(lm2, m);
        else              lm3 = fmaxf(lm3, m);
    }

    __shared__ float sred[4][8];
    float lm[4] = {lm0, lm1, lm2, lm3};
    int lane = threadIdx.x & 31, wid = threadIdx.x >> 5;
    #pragma unroll
    for (int g = 0; g < 4; g++) {
        float v = lm[g];
        #pragma unroll
        for (int o = 16; o; o >>= 1) v = fmaxf(v, __shfl_down_sync(0xffffffffu, v, o));
        if (lane == 0) sred[g][wid] = v;
    }
    __syncthreads();
    if (threadIdx.x < 4) {
        float v = sred[threadIdx.x][0];
        #pragma unroll
        for (int w = 1; w < 8; w++) v = fmaxf(v, sred[threadIdx.x][w]);
        g_coarse[(size_t)(b*CC + c)*CELLS + gy*4 + threadIdx.x] = v;
    }
}

// ---------------------------------------------------------------------------
// Kernel 2: per-batch importance, mask, keep, coords, and 224x224 mask table.
// ---------------------------------------------------------------------------
__global__ void k_mask(const float* __restrict__ logit_th,
                       float* __restrict__ out_keep,
                       float* __restrict__ out_coords) {
    int b = blockIdx.x, t = threadIdx.x;
    __shared__ float swarp[CELLS][8];
    __shared__ float simp[CELLS];
    __shared__ float smask[CELLS];

    // importance: sum over channels of coarse^2 per cell
    const float* cc = g_coarse + ((size_t)b*CC + t)*CELLS;
    float v[CELLS];
    #pragma unroll
    for (int n = 0; n < CELLS; n++) v[n] = cc[n];
    int lane = t & 31, wid = t >> 5;
    #pragma unroll
    for (int n = 0; n < CELLS; n++) {
        float s = v[n]*v[n];
        #pragma unroll
        for (int o = 16; o; o >>= 1) s += __shfl_down_sync(0xffffffffu, s, o);
        if (lane == 0) swarp[n][wid] = s;
    }
    __syncthreads();
    if (t < CELLS) {
        float s = 0.f;
        #pragma unroll
        for (int w = 0; w < 8; w++) s += swarp[t][w];
        simp[t] = sqrtf(s);
    }
    __syncthreads();
    if (t < CELLS) {
        float mn = simp[0], mx = simp[0];
        #pragma unroll
        for (int n = 1; n < CELLS; n++) { mn = fminf(mn, simp[n]); mx = fmaxf(mx, simp[n]); }
        float imp01 = (simp[t] - mn) / (mx - mn + 1e-8f);
        float th   = 1.f / (1.f + expf(-logit_th[NUM_LEVELS - 1]));
        float hard = (imp01 >= th) ? 1.f : 0.f;
        float soft = 1.f / (1.f + expf(-(imp01 - th) * 10.f));
        float bg   = (hard - soft) + soft;   // STE forward value
        float mask = fmaxf(bg, 0.f);
        smask[t] = mask;
        g_mask[b*CELLS + t] = mask;
        float keep = (mask > 0.5f) ? 1.f : 0.f;
        out_keep[b*CELLS + t] = keep;
        int r = t >> 2, cx = t & 3;          // cell n = gy*4 + gx -> (cx from gx, cy from gy)
        float4 co = make_float4((cx + 0.5f)*0.25f*keep, (r + 0.5f)*0.25f*keep,
                                0.25f*keep, 0.25f*keep);
        ((float4*)out_coords)[b*CELLS + t] = co;
    }
    __syncthreads();

    // bilinear (half-pixel, edge-clamped) upsample of 4x4 mask to 224x224
    float m[CELLS];
    #pragma unroll
    for (int n = 0; n < CELLS; n++) m[n] = smask[n];
    float* fm = (float*)g_fmask4 + (size_t)b*HW;
    for (int p = t; p < HW; p += 256) {
        int y = p / WW, xw = p - y*WW;
        float ty = fminf(fmaxf((y + 0.5f)*(1.f/56.f) - 0.5f, 0.f), 3.f);
        float tx = fminf(fmaxf((xw + 0.5f)*(1.f/56.f) - 0.5f, 0.f), 3.f);
        int jy = min((int)ty, 2); float fy = ty - (float)jy;
        int jx = min((int)tx, 2); float fx = tx - (float)jx;
        float top = m[jy*4+jx]*(1.f-fx)     + m[jy*4+jx+1]*fx;
        float bot = m[(jy+1)*4+jx]*(1.f-fx) + m[(jy+1)*4+jx+1]*fx;
        fm[p] = top*(1.f-fy) + bot*fy;
    }
}

// ---------------------------------------------------------------------------
// Kernel 3: LayerNorm + Linear over coarse cells, gated by keep.
// One block per (b, cell), thread = output feature.
// ---------------------------------------------------------------------------
__global__ void k_proj(const float* __restrict__ gamma, const float* __restrict__ beta,
                       const float* __restrict__ wproj, const float* __restrict__ bproj,
                       float* __restrict__ out_feats) {
    int bn = blockIdx.x;             // b*16 + n
    int b = bn >> 4, n = bn & 15;
    int t = threadIdx.x;
    __shared__ float sf[256];
    __shared__ float sred[8];

    float f = g_coarse[((size_t)b*CC + t)*CELLS + n];
    int lane = t & 31, wid = t >> 5;

    float s = f;
    #pragma unroll
    for (int o = 16; o; o >>= 1) s += __shfl_down_sync(0xffffffffu, s, o);
    if (lane == 0) sred[wid] = s;
    __syncthreads();
    float mean = 0.f;
    #pragma unroll
    for (int w = 0; w < 8; w++) mean += sred[w];
    mean *= (1.f/256.f);
    __syncthreads();

    float d = f - mean;
    s = d*d;
    #pragma unroll
    for (int o = 16; o; o >>= 1) s += __shfl_down_sync(0xffffffffu, s, o);
    if (lane == 0) sred[wid] = s;
    __syncthreads();
    float var = 0.f;
    #pragma unroll
    for (int w = 0; w < 8; w++) var += sred[w];
    var *= (1.f/256.f);

    sf[t] = d * rsqrtf(var + 1e-5f) * gamma[t] + beta[t];
    __syncthreads();

    float acc = bproj[t];
    #pragma unroll 8
    for (int c = 0; c < 256; c++) acc = fmaf(sf[c], wproj[c*256 + t], acc);
    float keep = (g_mask[bn] > 0.5f) ? 1.f : 0.f;
    out_feats[(size_t)bn*256 + t] = acc * keep;
}

// ---------------------------------------------------------------------------
// Kernel 4: out_sparse = x * upsampled_mask (float4 streaming)
// ---------------------------------------------------------------------------
__global__ void k_sparse(const float4* __restrict__ x4, float4* __restrict__ o4) {
    unsigned int i = blockIdx.x * 256u + threadIdx.x;   // < 25,690,112
    const unsigned int per_b = CC * HW4;                // 3,211,264
    unsigned int b = i / per_b;
    unsigned int rem = i - b * per_b;
    unsigned int pix4 = rem % HW4;
    float4 m = g_fmask4[b*HW4 + pix4];
    float4 v = x4[i];
    o4[i] = make_float4(v.x*m.x, v.y*m.y, v.z*m.z, v.w*m.w);
}

// ---------------------------------------------------------------------------
extern "C" void kernel_launch(void* const* d_in, const int* in_sizes, int n_in,
                              void* d_out, int out_size) {
    const float* x     = (const float*)d_in[0];
    const float* logit = (const float*)d_in[1];
    const float* gamma = (const float*)d_in[2];
    const float* beta  = (const float*)d_in[3];
    const float* wproj = (const float*)d_in[4];
    const float* bproj = (const float*)d_in[5];

    float* out        = (float*)d_out;
    float* out_sparse = out;                                   // 102,760,448
    float* out_feats  = out + (size_t)BB*CC*HW;                // +32768
    float* out_coords = out_feats + BB*CELLS*256;              // +512
    float* out_keep   = out_coords + BB*CELLS*4;               // +128

    k_pool  <<<BB*CC*4, 256>>>(x);
    k_mask  <<<BB, 256>>>(logit, out_keep, out_coords);
    k_proj  <<<BB*CELLS, 256>>>(gamma, beta, wproj, bproj, out_feats);
    k_sparse<<<(BB*CC*HW/4 + 255)/256, 256>>>((const float4*)x, (float4*)out_sparse);
}

// round 3
// speedup vs baseline: 1.1217x; 1.1217x over previous
#include <cuda_runtime.h>
#include <math.h>

#define BB 8
#define CC 256
#define HH 224
#define WW 224
#define CELLS 16
#define KH 56
#define HW (HH*WW)
#define HW4 (HW/4)
#define NUM_LEVELS 3

// scratch (no allocations allowed)
__device__ float g_coarse[BB*CC*CELLS];   // [b][c][cell]
__device__ float g_mask[BB*CELLS];

// ---------------------------------------------------------------------------
// Kernel 1: grid max pool for ONE batch. One block per (c, gy): a contiguous
// 56x224 slab. 224 threads so the float4-column index (i % 56) is loop
// invariant: i = t + k*224 and 224 = 4*56.
// ---------------------------------------------------------------------------
__global__ void k_pool(const float* __restrict__ x, int b) {
    int bid = blockIdx.x;             // c*4 + gy
    int gy = bid & 3;
    int c  = bid >> 2;
    int t  = threadIdx.x;             // 0..223
    const float4* src = (const float4*)(x + ((size_t)(b*CC + c)*HH + gy*KH)*WW);

    float lm = -3.402823466e38f;
    #pragma unroll
    for (int k = 0; k < 14; k++) {    // 14*224 = 3136 float4 = whole slab
        float4 v = src[t + k*224];
        lm = fmaxf(lm, fmaxf(fmaxf(v.x, v.y), fmaxf(v.z, v.w)));
    }

    __shared__ float sm[224];
    sm[t] = lm;
    __syncthreads();
    if (t < 4) {                      // t = gx; its float4-cols are [14t, 14t+14)
        float v = -3.402823466e38f;
        #pragma unroll
        for (int r = 0; r < 4; r++)
            #pragma unroll
            for (int q = 0; q < 14; q++)
                v = fmaxf(v, sm[r*56 + t*14 + q]);
        g_coarse[((size_t)(b*CC + c))*CELLS + gy*4 + t] = v;
    }
}

// ---------------------------------------------------------------------------
// Kernel 2: per-batch importance -> mask/keep/coords (1 block).
// ---------------------------------------------------------------------------
__global__ void k_mask(const float* __restrict__ logit_th,
                       float* __restrict__ out_keep,
                       float* __restrict__ out_coords, int b) {
    int t = threadIdx.x;
    __shared__ float swarp[CELLS][8];
    __shared__ float simp[CELLS];

    const float* cc = g_coarse + ((size_t)b*CC + t)*CELLS;
    float v[CELLS];
    #pragma unroll
    for (int n = 0; n < CELLS; n++) v[n] = cc[n];
    int lane = t & 31, wid = t >> 5;
    #pragma unroll
    for (int n = 0; n < CELLS; n++) {
        float s = v[n]*v[n];
        #pragma unroll
        for (int o = 16; o; o >>= 1) s += __shfl_down_sync(0xffffffffu, s, o);
        if (lane == 0) swarp[n][wid] = s;
    }
    __syncthreads();
    if (t < CELLS) {
        float s = 0.f;
        #pragma unroll
        for (int w = 0; w < 8; w++) s += swarp[t][w];
        simp[t] = sqrtf(s);
    }
    __syncthreads();
    if (t < CELLS) {
        float mn = simp[0], mx = simp[0];
        #pragma unroll
        for (int n = 1; n < CELLS; n++) { mn = fminf(mn, simp[n]); mx = fmaxf(mx, simp[n]); }
        float imp01 = (simp[t] - mn) / (mx - mn + 1e-8f);
        float th   = 1.f / (1.f + expf(-logit_th[NUM_LEVELS - 1]));
        float hard = (imp01 >= th) ? 1.f : 0.f;
        float soft = 1.f / (1.f + expf(-(imp01 - th) * 10.f));
        float mask = fmaxf((hard - soft) + soft, 0.f);
        g_mask[b*CELLS + t] = mask;
        float keep = (mask > 0.5f) ? 1.f : 0.f;
        out_keep[b*CELLS + t] = keep;
        int r = t >> 2, cx = t & 3;
        ((float4*)out_coords)[b*CELLS + t] =
            make_float4((cx + 0.5f)*0.25f*keep, (r + 0.5f)*0.25f*keep,
                        0.25f*keep, 0.25f*keep);
    }
}

// ---------------------------------------------------------------------------
// Kernel 3: LayerNorm + Linear over coarse cells, gated by keep.
// ---------------------------------------------------------------------------
__global__ void k_proj(const float* __restrict__ gamma, const float* __restrict__ beta,
                       const float* __restrict__ wproj, const float* __restrict__ bproj,
                       float* __restrict__ out_feats) {
    int bn = blockIdx.x;             // b*16 + n
    int b = bn >> 4, n = bn & 15;
    int t = threadIdx.x;
    __shared__ float sf[256];
    __shared__ float sred[8];

    float f = g_coarse[((size_t)b*CC + t)*CELLS + n];
    int lane = t & 31, wid = t >> 5;

    float s = f;
    #pragma unroll
    for (int o = 16; o; o >>= 1) s += __shfl_down_sync(0xffffffffu, s, o);
    if (lane == 0) sred[wid] = s;
    __syncthreads();
    float mean = 0.f;
    #pragma unroll
    for (int w = 0; w < 8; w++) mean += sred[w];
    mean *= (1.f/256.f);
    __syncthreads();

    float d = f - mean;
    s = d*d;
    #pragma unroll
    for (int o = 16; o; o >>= 1) s += __shfl_down_sync(0xffffffffu, s, o);
    if (lane == 0) sred[wid] = s;
    __syncthreads();
    float var = 0.f;
    #pragma unroll
    for (int w = 0; w < 8; w++) var += sred[w];
    var *= (1.f/256.f);

    sf[t] = d * rsqrtf(var + 1e-5f) * gamma[t] + beta[t];
    __syncthreads();

    float acc = bproj[t];
    #pragma unroll 8
    for (int c = 0; c < 256; c++) acc = fmaf(sf[c], wproj[c*256 + t], acc);
    float keep = (g_mask[bn] > 0.5f) ? 1.f : 0.f;
    out_feats[(size_t)bn*256 + t] = acc * keep;
}

// ---------------------------------------------------------------------------
// Kernel 4: out = x * bilinear(mask) for ONE batch, mask computed inline.
// grid = (HW4/256, CC). Evict-first hints: x[b] and out[b] are never re-read.
// ---------------------------------------------------------------------------
__global__ void k_sparse(const float4* __restrict__ x4, float4* __restrict__ o4, int b) {
    __shared__ float m[CELLS];
    if (threadIdx.x < CELLS) m[threadIdx.x] = g_mask[b*CELLS + threadIdx.x];
    __syncthreads();

    int pix4 = blockIdx.x * 256 + threadIdx.x;          // 0..50175
    int ch   = blockIdx.y;
    size_t idx = ((size_t)(b*CC + ch))*HW4 + pix4;

    int y  = pix4 / 56;                                  // pix/224, exact
    int xw = pix4*4 - y*224;

    float ty = fminf(fmaxf((y + 0.5f)*(1.f/56.f) - 0.5f, 0.f), 3.f);
    int jy = min((int)ty, 2);
    float fy = ty - (float)jy;
    // y-interpolated row of 4 cell values
    float r0 = m[jy*4+0] + (m[(jy+1)*4+0] - m[jy*4+0])*fy;
    float r1 = m[jy*4+1] + (m[(jy+1)*4+1] - m[jy*4+1])*fy;
    float r2 = m[jy*4+2] + (m[(jy+1)*4+2] - m[jy*4+2])*fy;
    float r3 = m[jy*4+3] + (m[(jy+1)*4+3] - m[jy*4+3])*fy;

    float mk[4];
    #pragma unroll
    for (int i = 0; i < 4; i++) {
        float tx = fminf(fmaxf((xw + i + 0.5f)*(1.f/56.f) - 0.5f, 0.f), 3.f);
        int jx = min((int)tx, 2);
        float fx = tx - (float)jx;
        float a = (jx == 0) ? r0 : (jx == 1) ? r1 : r2;
        float c = (jx == 0) ? r1 : (jx == 1) ? r2 : r3;
        mk[i] = a + (c - a)*fx;
    }

    float4 v = __ldcs(&x4[idx]);
    __stcs(&o4[idx], make_float4(v.x*mk[0], v.y*mk[1], v.z*mk[2], v.w*mk[3]));
}

// ---------------------------------------------------------------------------
extern "C" void kernel_launch(void* const* d_in, const int* in_sizes, int n_in,
                              void* d_out, int out_size) {
    const float* x     = (const float*)d_in[0];
    const float* logit = (const float*)d_in[1];
    const float* gamma = (const float*)d_in[2];
    const float* beta  = (const float*)d_in[3];
    const float* wproj = (const float*)d_in[4];
    const float* bproj = (const float*)d_in[5];

    float* out        = (float*)d_out;
    float* out_sparse = out;
    float* out_feats  = out + (size_t)BB*CC*HW;
    float* out_coords = out_feats + BB*CELLS*256;
    float* out_keep   = out_coords + BB*CELLS*4;

    dim3 gsp(HW4/256, CC);   // (196, 256)
    for (int b = 0; b < BB; b++) {
        k_pool  <<<CC*4, 224>>>(x, b);
        k_mask  <<<1, 256>>>(logit, out_keep, out_coords, b);
        k_sparse<<<gsp, 256>>>((const float4*)x, (float4*)out_sparse, b);
    }
    k_proj<<<BB*CELLS, 256>>>(gamma, beta, wproj, bproj, out_feats);
}

// round 6
// speedup vs baseline: 1.1745x; 1.0471x over previous
#include <cuda_runtime.h>
#include <math.h>

#define BB 8
#define CC 256
#define HH 224
#define WW 224
#define CELLS 16
#define KH 56
#define HW (HH*WW)
#define HW4 (HW/4)
#define NUM_LEVELS 3

// scratch (no allocations allowed)
__device__ float g_coarse[BB*CC*CELLS];   // [b][c][cell]
__device__ float g_mask[BB*CELLS];

// ---------------------------------------------------------------------------
// Kernel 1: grid max pool for ONE batch. One block per (c, gy): a contiguous
// 56x224 slab. 224 threads; 14 float4 loads per thread, explicitly batched
// into a register array for MLP=14 (dependent-fmax chain killed batching
// before: regs=31 -> serialized loads -> only 57% DRAM).
// ---------------------------------------------------------------------------
__global__ void k_pool(const float* __restrict__ x, int b) {
    int bid = blockIdx.x;             // c*4 + gy
    int gy = bid & 3;
    int c  = bid >> 2;
    int t  = threadIdx.x;             // 0..223
    const float4* src = (const float4*)(x + ((size_t)(b*CC + c)*HH + gy*KH)*WW);

    float4 v[14];
    #pragma unroll
    for (int k = 0; k < 14; k++) v[k] = src[t + k*224];   // front-batched

    float lm = -3.402823466e38f;
    #pragma unroll
    for (int k = 0; k < 14; k++)
        lm = fmaxf(lm, fmaxf(fmaxf(v[k].x, v[k].y), fmaxf(v[k].z, v[k].w)));

    __shared__ float sm[224];
    sm[t] = lm;
    __syncthreads();
    if (t < 4) {                      // t = gx; its float4-cols are [14t, 14t+14)
        float m = -3.402823466e38f;
        #pragma unroll
        for (int r = 0; r < 4; r++)
            #pragma unroll
            for (int q = 0; q < 14; q++)
                m = fmaxf(m, sm[r*56 + t*14 + q]);
        g_coarse[((size_t)(b*CC + c))*CELLS + gy*4 + t] = m;
    }
}

// ---------------------------------------------------------------------------
// Kernel 2: per-batch importance -> mask/keep/coords (1 block).
// ---------------------------------------------------------------------------
__global__ void k_mask(const float* __restrict__ logit_th,
                       float* __restrict__ out_keep,
                       float* __restrict__ out_coords, int b) {
    int t = threadIdx.x;
    __shared__ float swarp[CELLS][8];
    __shared__ float simp[CELLS];

    const float* cc = g_coarse + ((size_t)b*CC + t)*CELLS;
    float v[CELLS];
    #pragma unroll
    for (int n = 0; n < CELLS; n++) v[n] = cc[n];
    int lane = t & 31, wid = t >> 5;
    #pragma unroll
    for (int n = 0; n < CELLS; n++) {
        float s = v[n]*v[n];
        #pragma unroll
        for (int o = 16; o; o >>= 1) s += __shfl_down_sync(0xffffffffu, s, o);
        if (lane == 0) swarp[n][wid] = s;
    }
    __syncthreads();
    if (t < CELLS) {
        float s = 0.f;
        #pragma unroll
        for (int w = 0; w < 8; w++) s += swarp[t][w];
        simp[t] = sqrtf(s);
    }
    __syncthreads();
    if (t < CELLS) {
        float mn = simp[0], mx = simp[0];
        #pragma unroll
        for (int n = 1; n < CELLS; n++) { mn = fminf(mn, simp[n]); mx = fmaxf(mx, simp[n]); }
        float imp01 = (simp[t] - mn) / (mx - mn + 1e-8f);
        float th   = 1.f / (1.f + expf(-logit_th[NUM_LEVELS - 1]));
        float hard = (imp01 >= th) ? 1.f : 0.f;
        float soft = 1.f / (1.f + expf(-(imp01 - th) * 10.f));
        float mask = fmaxf((hard - soft) + soft, 0.f);
        g_mask[b*CELLS + t] = mask;
        float keep = (mask > 0.5f) ? 1.f : 0.f;
        out_keep[b*CELLS + t] = keep;
        int r = t >> 2, cx = t & 3;
        ((float4*)out_coords)[b*CELLS + t] =
            make_float4((cx + 0.5f)*0.25f*keep, (r + 0.5f)*0.25f*keep,
                        0.25f*keep, 0.25f*keep);
    }
}

// ---------------------------------------------------------------------------
// Kernel 3: LayerNorm + Linear over coarse cells, gated by keep.
// ---------------------------------------------------------------------------
__global__ void k_proj(const float* __restrict__ gamma, const float* __restrict__ beta,
                       const float* __restrict__ wproj, const float* __restrict__ bproj,
                       float* __restrict__ out_feats) {
    int bn = blockIdx.x;             // b*16 + n
    int b = bn >> 4, n = bn & 15;
    int t = threadIdx.x;
    __shared__ float sf[256];
    __shared__ float sred[8];

    float f = g_coarse[((size_t)b*CC + t)*CELLS + n];
    int lane = t & 31, wid = t >> 5;

    float s = f;
    #pragma unroll
    for (int o = 16; o; o >>= 1) s += __shfl_down_sync(0xffffffffu, s, o);
    if (lane == 0) sred[wid] = s;
    __syncthreads();
    float mean = 0.f;
    #pragma unroll
    for (int w = 0; w < 8; w++) mean += sred[w];
    mean *= (1.f/256.f);
    __syncthreads();

    float d = f - mean;
    s = d*d;
    #pragma unroll
    for (int o = 16; o; o >>= 1) s += __shfl_down_sync(0xffffffffu, s, o);
    if (lane == 0) sred[wid] = s;
    __syncthreads();
    float var = 0.f;
    #pragma unroll
    for (int w = 0; w < 8; w++) var += sred[w];
    var *= (1.f/256.f);

    sf[t] = d * rsqrtf(var + 1e-5f) * gamma[t] + beta[t];
    __syncthreads();

    float acc = bproj[t];
    #pragma unroll 8
    for (int c = 0; c < 256; c++) acc = fmaf(sf[c], wproj[c*256 + t], acc);
    float keep = (g_mask[bn] > 0.5f) ? 1.f : 0.f;
    out_feats[(size_t)bn*256 + t] = acc * keep;
}

// ---------------------------------------------------------------------------
// Kernel 4: out = x * bilinear(mask) for ONE batch, mask computed inline.
// x read with evict-first (last use, should hit L2 from k_pool), out streamed.
// ---------------------------------------------------------------------------
__global__ void k_sparse(const float4* __restrict__ x4, float4* __restrict__ o4, int b) {
    __shared__ float m[CELLS];
    if (threadIdx.x < CELLS) m[threadIdx.x] = g_mask[b*CELLS + threadIdx.x];
    __syncthreads();

    int pix4 = blockIdx.x * 256 + threadIdx.x;          // 0..50175
    int ch   = blockIdx.y;
    size_t idx = ((size_t)(b*CC + ch))*HW4 + pix4;

    int y  = pix4 / 56;                                  // pix/224, exact
    int xw = pix4*4 - y*224;

    float ty = fminf(fmaxf((y + 0.5f)*(1.f/56.f) - 0.5f, 0.f), 3.f);
    int jy = min((int)ty, 2);
    float fy = ty - (float)jy;
    float r0 = m[jy*4+0] + (m[(jy+1)*4+0] - m[jy*4+0])*fy;
    float r1 = m[jy*4+1] + (m[(jy+1)*4+1] - m[jy*4+1])*fy;
    float r2 = m[jy*4+2] + (m[(jy+1)*4+2] - m[jy*4+2])*fy;
    float r3 = m[jy*4+3] + (m[(jy+1)*4+3] - m[jy*4+3])*fy;

    float mk[4];
    #pragma unroll
    for (int i = 0; i < 4; i++) {
        float tx = fminf(fmaxf((xw + i + 0.5f)*(1.f/56.f) - 0.5f, 0.f), 3.f);
        int jx = min((int)tx, 2);
        float fx = tx - (float)jx;
        float a = (jx == 0) ? r0 : (jx == 1) ? r1 : r2;
        float c = (jx == 0) ? r1 : (jx == 1) ? r2 : r3;
        mk[i] = a + (c - a)*fx;
    }

    float4 v = __ldcs(&x4[idx]);
    __stcs(&o4[idx], make_float4(v.x*mk[0], v.y*mk[1], v.z*mk[2], v.w*mk[3]));
}

// ---------------------------------------------------------------------------
// Fork-join multi-stream capture: pool/mask chain on the capture stream,
// sparse(b) on a second stream gated by an event after mask(b). This lets
// pool(b+1) (DRAM reads) overlap sparse(b) (L2 reads + DRAM writes).
// ---------------------------------------------------------------------------
extern "C" void kernel_launch(void* const* d_in, const int* in_sizes, int n_in,
                              void* d_out, int out_size) {
    const float* x     = (const float*)d_in[0];
    const float* logit = (const float*)d_in[1];
    const float* gamma = (const float*)d_in[2];
    const float* beta  = (const float*)d_in[3];
    const float* wproj = (const float*)d_in[4];
    const float* bproj = (const float*)d_in[5];

    float* out        = (float*)d_out;
    float* out_sparse = out;
    float* out_feats  = out + (size_t)BB*CC*HW;
    float* out_coords = out_feats + BB*CELLS*256;
    float* out_keep   = out_coords + BB*CELLS*4;

    // lazily created once (host-side resources only; no device allocations)
    static cudaStream_t s1 = nullptr;
    static cudaEvent_t evM[BB];
    static cudaEvent_t evJ = nullptr;
    if (s1 == nullptr) {
        cudaStreamCreateWithFlags(&s1, cudaStreamNonBlocking);
        for (int b = 0; b < BB; b++)
            cudaEventCreateWithFlags(&evM[b], cudaEventDisableTiming);
        cudaEventCreateWithFlags(&evJ, cudaEventDisableTiming);
    }

    dim3 gsp(HW4/256, CC);   // (196, 256)
    for (int b = 0; b < BB; b++) {
        k_pool<<<CC*4, 224>>>(x, b);
        k_mask<<<1, 256>>>(logit, out_keep, out_coords, b);
        cudaEventRecord(evM[b], 0);
        cudaStreamWaitEvent(s1, evM[b], 0);
        k_sparse<<<gsp, 256, 0, s1>>>((const float4*)x, (float4*)out_sparse, b);
    }
    // join the side stream back before the final (independent) proj kernel
    cudaEventRecord(evJ, s1);
    cudaStreamWaitEvent(0, evJ, 0);
    k_proj<<<BB*CELLS, 256>>>(gamma, beta, wproj, bproj, out_feats);
}

// round 11
// speedup vs baseline: 1.1831x; 1.0073x over previous
#include <cuda_runtime.h>
#include <math.h>

#define BB 8
#define CC 256
#define HH 224
#define WW 224
#define CELLS 16
#define KH 56
#define HW (HH*WW)
#define HW4 (HW/4)
#define NUM_LEVELS 3

// scratch (no allocations allowed)
__device__ float g_coarse[BB*CC*CELLS];   // [b][c][cell]
__device__ float g_mask[BB*CELLS];

// 256-bit evict-last load (sm_103a only encodes the L2 policy on v8.b32/v4.b64)
__device__ __forceinline__ void ld_evict_last8(const float* p, float* v) {
    unsigned r0,r1,r2,r3,r4,r5,r6,r7;
    asm volatile("ld.global.nc.L2::evict_last.v8.b32 {%0,%1,%2,%3,%4,%5,%6,%7}, [%8];"
                 : "=r"(r0),"=r"(r1),"=r"(r2),"=r"(r3),
                   "=r"(r4),"=r"(r5),"=r"(r6),"=r"(r7) : "l"(p));
    v[0]=__uint_as_float(r0); v[1]=__uint_as_float(r1);
    v[2]=__uint_as_float(r2); v[3]=__uint_as_float(r3);
    v[4]=__uint_as_float(r4); v[5]=__uint_as_float(r5);
    v[6]=__uint_as_float(r6); v[7]=__uint_as_float(r7);
}

// ---------------------------------------------------------------------------
// Kernel 1: grid max pool for ONE batch, pinning x[b] evict-last in L2.
// One block per (c, gy): contiguous 56x224 slab = 1568 x 32B chunks.
// 224 threads x 7 chunks, i = t + k*224. 224 = 8*28, so chunk-in-row (i%28)
// and hence the cell column gx = (i%28)/7 is loop-invariant per thread.
// ---------------------------------------------------------------------------
__global__ void __launch_bounds__(224, 2) k_pool(const float* __restrict__ x, int b) {
    int bid = blockIdx.x;             // c*4 + gy
    int gy = bid & 3;
    int c  = bid >> 2;
    int t  = threadIdx.x;             // 0..223
    const float* src = x + ((size_t)(b*CC + c)*HH + gy*KH)*WW;

    float v[7][8];
    #pragma unroll
    for (int k = 0; k < 7; k++)
        ld_evict_last8(src + (t + k*224)*8, v[k]);   // front-batched 32B loads

    float lm = -3.402823466e38f;
    #pragma unroll
    for (int k = 0; k < 7; k++) {
        float m01 = fmaxf(v[k][0], v[k][1]), m23 = fmaxf(v[k][2], v[k][3]);
        float m45 = fmaxf(v[k][4], v[k][5]), m67 = fmaxf(v[k][6], v[k][7]);
        lm = fmaxf(lm, fmaxf(fmaxf(m01, m23), fmaxf(m45, m67)));
    }

    __shared__ float sm[224];
    sm[t] = lm;                       // thread t: column chunk t%28, gx=(t%28)/7
    __syncthreads();
    if (t < 4) {                      // t = gx; its chunk cols are [7t, 7t+7)
        float m = -3.402823466e38f;
        #pragma unroll
        for (int r = 0; r < 8; r++)
            #pragma unroll
            for (int q = 0; q < 7; q++)
                m = fmaxf(m, sm[r*28 + t*7 + q]);
        g_coarse[((size_t)(b*CC + c))*CELLS + gy*4 + t] = m;
    }
}

// ---------------------------------------------------------------------------
// Kernel 2: per-batch importance -> mask/keep/coords (1 block).
// ---------------------------------------------------------------------------
__global__ void k_mask(const float* __restrict__ logit_th,
                       float* __restrict__ out_keep,
                       float* __restrict__ out_coords, int b) {
    int t = threadIdx.x;
    __shared__ float swarp[CELLS][8];
    __shared__ float simp[CELLS];

    const float* cc = g_coarse + ((size_t)b*CC + t)*CELLS;
    float v[CELLS];
    #pragma unroll
    for (int n = 0; n < CELLS; n++) v[n] = cc[n];
    int lane = t & 31, wid = t >> 5;
    #pragma unroll
    for (int n = 0; n < CELLS; n++) {
        float s = v[n]*v[n];
        #pragma unroll
        for (int o = 16; o; o >>= 1) s += __shfl_down_sync(0xffffffffu, s, o);
        if (lane == 0) swarp[n][wid] = s;
    }
    __syncthreads();
    if (t < CELLS) {
        float s = 0.f;
        #pragma unroll
        for (int w = 0; w < 8; w++) s += swarp[t][w];
        simp[t] = sqrtf(s);
    }
    __syncthreads();
    if (t < CELLS) {
        float mn = simp[0], mx = simp[0];
        #pragma unroll
        for (int n = 1; n < CELLS; n++) { mn = fminf(mn, simp[n]); mx = fmaxf(mx, simp[n]); }
        float imp01 = (simp[t] - mn) / (mx - mn + 1e-8f);
        float th   = 1.f / (1.f + expf(-logit_th[NUM_LEVELS - 1]));
        float hard = (imp01 >= th) ? 1.f : 0.f;
        float soft = 1.f / (1.f + expf(-(imp01 - th) * 10.f));
        float mask = fmaxf((hard - soft) + soft, 0.f);
        g_mask[b*CELLS + t] = mask;
        float keep = (mask > 0.5f) ? 1.f : 0.f;
        out_keep[b*CELLS + t] = keep;
        int r = t >> 2, cx = t & 3;
        ((float4*)out_coords)[b*CELLS + t] =
            make_float4((cx + 0.5f)*0.25f*keep, (r + 0.5f)*0.25f*keep,
                        0.25f*keep, 0.25f*keep);
    }
}

// ---------------------------------------------------------------------------
// Kernel 3: LayerNorm + Linear over coarse cells, gated by keep.
// ---------------------------------------------------------------------------
__global__ void k_proj(const float* __restrict__ gamma, const float* __restrict__ beta,
                       const float* __restrict__ wproj, const float* __restrict__ bproj,
                       float* __restrict__ out_feats) {
    int bn = blockIdx.x;             // b*16 + n
    int b = bn >> 4, n = bn & 15;
    int t = threadIdx.x;
    __shared__ float sf[256];
    __shared__ float sred[8];

    float f = g_coarse[((size_t)b*CC + t)*CELLS + n];
    int lane = t & 31, wid = t >> 5;

    float s = f;
    #pragma unroll
    for (int o = 16; o; o >>= 1) s += __shfl_down_sync(0xffffffffu, s, o);
    if (lane == 0) sred[wid] = s;
    __syncthreads();
    float mean = 0.f;
    #pragma unroll
    for (int w = 0; w < 8; w++) mean += sred[w];
    mean *= (1.f/256.f);
    __syncthreads();

    float d = f - mean;
    s = d*d;
    #pragma unroll
    for (int o = 16; o; o >>= 1) s += __shfl_down_sync(0xffffffffu, s, o);
    if (lane == 0) sred[wid] = s;
    __syncthreads();
    float var = 0.f;
    #pragma unroll
    for (int w = 0; w < 8; w++) var += sred[w];
    var *= (1.f/256.f);

    sf[t] = d * rsqrtf(var + 1e-5f) * gamma[t] + beta[t];
    __syncthreads();

    float acc = bproj[t];
    #pragma unroll 8
    for (int c = 0; c < 256; c++) acc = fmaf(sf[c], wproj[c*256 + t], acc);
    float keep = (g_mask[bn] > 0.5f) ? 1.f : 0.f;
    out_feats[(size_t)bn*256 + t] = acc * keep;
}

// ---------------------------------------------------------------------------
// Kernel 4: out = x * bilinear(mask) for ONE batch, mask computed inline.
// x re-read evict-first (hits the pinned lines, then demotes them); out
// streamed evict-first.
// ---------------------------------------------------------------------------
__global__ void k_sparse(const float4* __restrict__ x4, float4* __restrict__ o4, int b) {
    __shared__ float m[CELLS];
    if (threadIdx.x < CELLS) m[threadIdx.x] = g_mask[b*CELLS + threadIdx.x];
    __syncthreads();

    int pix4 = blockIdx.x * 256 + threadIdx.x;          // 0..50175
    int ch   = blockIdx.y;
    size_t idx = ((size_t)(b*CC + ch))*HW4 + pix4;

    int y  = pix4 / 56;                                  // pix/224, exact
    int xw = pix4*4 - y*224;

    float ty = fminf(fmaxf((y + 0.5f)*(1.f/56.f) - 0.5f, 0.f), 3.f);
    int jy = min((int)ty, 2);
    float fy = ty - (float)jy;
    float r0 = m[jy*4+0] + (m[(jy+1)*4+0] - m[jy*4+0])*fy;
    float r1 = m[jy*4+1] + (m[(jy+1)*4+1] - m[jy*4+1])*fy;
    float r2 = m[jy*4+2] + (m[(jy+1)*4+2] - m[jy*4+2])*fy;
    float r3 = m[jy*4+3] + (m[(jy+1)*4+3] - m[jy*4+3])*fy;

    float mk[4];
    #pragma unroll
    for (int i = 0; i < 4; i++) {
        float tx = fminf(fmaxf((xw + i + 0.5f)*(1.f/56.f) - 0.5f, 0.f), 3.f);
        int jx = min((int)tx, 2);
        float fx = tx - (float)jx;
        float a = (jx == 0) ? r0 : (jx == 1) ? r1 : r2;
        float c = (jx == 0) ? r1 : (jx == 1) ? r2 : r3;
        mk[i] = a + (c - a)*fx;
    }

    float4 v = __ldcs(&x4[idx]);
    __stcs(&o4[idx], make_float4(v.x*mk[0], v.y*mk[1], v.z*mk[2], v.w*mk[3]));
}

// ---------------------------------------------------------------------------
// Fork-join multi-stream capture: pool/mask on capture stream, sparse(b) on a
// second stream after mask(b). With x pinned evict-last, sparse reads hit L2
// and its DRAM use is writes-only -> real overlap with pool(b+1) reads.
// ---------------------------------------------------------------------------
extern "C" void kernel_launch(void* const* d_in, const int* in_sizes, int n_in,
                              void* d_out, int out_size) {
    const float* x     = (const float*)d_in[0];
    const float* logit = (const float*)d_in[1];
    const float* gamma = (const float*)d_in[2];
    const float* beta  = (const float*)d_in[3];
    const float* wproj = (const float*)d_in[4];
    const float* bproj = (const float*)d_in[5];

    float* out        = (float*)d_out;
    float* out_sparse = out;
    float* out_feats  = out + (size_t)BB*CC*HW;
    float* out_coords = out_feats + BB*CELLS*256;
    float* out_keep   = out_coords + BB*CELLS*4;

    static cudaStream_t s1 = nullptr;
    static cudaEvent_t evM[BB];
    static cudaEvent_t evJ = nullptr;
    if (s1 == nullptr) {
        cudaStreamCreateWithFlags(&s1, cudaStreamNonBlocking);
        for (int b = 0; b < BB; b++)
            cudaEventCreateWithFlags(&evM[b], cudaEventDisableTiming);
        cudaEventCreateWithFlags(&evJ, cudaEventDisableTiming);
    }

    dim3 gsp(HW4/256, CC);   // (196, 256)
    for (int b = 0; b < BB; b++) {
        k_pool<<<CC*4, 224>>>(x, b);
        k_mask<<<1, 256>>>(logit, out_keep, out_coords, b);
        cudaEventRecord(evM[b], 0);
        cudaStreamWaitEvent(s1, evM[b], 0);
        k_sparse<<<gsp, 256, 0, s1>>>((const float4*)x, (float4*)out_sparse, b);
    }
    cudaEventRecord(evJ, s1);
    cudaStreamWaitEvent(0, evJ, 0);
    k_proj<<<BB*CELLS, 256>>>(gamma, beta, wproj, bproj, out_feats);
}

// round 12
// speedup vs baseline: 1.2025x; 1.0164x over previous
#include <cuda_runtime.h>
#include <math.h>
#include <float.h>

#define BB 8
#define CC 256
#define HH 224
#define WW 224
#define CELLS 16
#define HW (HH*WW)
#define NUM_LEVELS 3
#define GRID_PER_B 512          // (c, gh): 256 channels x 2 half-channels

// scratch (no allocations allowed)
__device__ float    g_coarse[BB*CC*CELLS];  // [b][c][cell]
__device__ float    g_mask[BB*CELLS];
__device__ unsigned g_counter[BB];          // monotonic across replays
__device__ unsigned g_flag[BB];             // monotonic epoch per batch

// ---------------------------------------------------------------------------
// Fused per-batch kernel: pool (read x once) -> last-block mask epilogue ->
// grid-wide spin -> sparse multiply re-reading the SAME slab (L2-hot).
// 512 blocks x 224 threads, __launch_bounds__(224,4) guarantees co-residency.
// ---------------------------------------------------------------------------
__global__ void __launch_bounds__(224, 4)
k_fused(const float* __restrict__ x, float4* __restrict__ o4,
        const float* __restrict__ logit_th,
        float* __restrict__ out_keep, float* __restrict__ out_coords, int b)
{
    const float4* x4 = (const float4*)x;
    int bid = blockIdx.x;          // c*2 + gh
    int gh  = bid & 1;
    int c   = bid >> 1;
    int t   = threadIdx.x;         // 0..223

    __shared__ unsigned s_epoch;
    __shared__ float    sm[224];
    __shared__ float    sw[CELLS][7];
    __shared__ float    simp[CELLS];
    __shared__ float    s_m[CELLS];
    __shared__ int      s_last;

    if (t == 0) s_epoch = *((volatile unsigned*)&g_flag[b]);

    // ---- Phase 1: pool two 56-row slabs (rows gh*112 + s*56 ...) ----------
    // slab = 3136 float4; thread t handles i = t + j*224, j<14.
    // 224 = 4*56 -> col4 = t%56 const; row-in-slab = t/56 + j*4.
    #pragma unroll
    for (int s = 0; s < 2; s++) {
        size_t base4 = ((size_t)(b*CC + c)*HH + gh*112 + s*56) * 56;
        float lm = -FLT_MAX;
        #pragma unroll
        for (int w = 0; w < 2; w++) {               // 2 waves of 7 batched loads
            float4 v[7];
            #pragma unroll
            for (int k = 0; k < 7; k++) v[k] = __ldg(&x4[base4 + t + (w*7 + k)*224]);
            #pragma unroll
            for (int k = 0; k < 7; k++)
                lm = fmaxf(lm, fmaxf(fmaxf(v[k].x, v[k].y), fmaxf(v[k].z, v[k].w)));
        }
        __syncthreads();                            // smem reuse guard
        sm[t] = lm;
        __syncthreads();
        if (t < 4) {                                // t = gx; cols [14t,14t+14)
            float m = -FLT_MAX;
            #pragma unroll
            for (int r = 0; r < 4; r++)
                #pragma unroll
                for (int q = 0; q < 14; q++)
                    m = fmaxf(m, sm[r*56 + t*14 + q]);
            g_coarse[((size_t)(b*CC + c))*CELLS + (gh*2 + s)*4 + t] = m;
        }
    }

    __threadfence();
    if (t == 0) {
        unsigned old = atomicAdd(&g_counter[b], 1u);
        s_last = ((old & (GRID_PER_B - 1u)) == GRID_PER_B - 1u) ? 1 : 0;
    }
    __syncthreads();

    // ---- Phase 2: last block computes importance -> mask -> keep/coords ---
    if (s_last) {
        float acc[CELLS];
        #pragma unroll
        for (int n = 0; n < CELLS; n++) acc[n] = 0.f;
        for (int ch = t; ch < CC; ch += 224) {
            const float* row = g_coarse + ((size_t)b*CC + ch)*CELLS;
            #pragma unroll
            for (int n = 0; n < CELLS; n++) { float v = row[n]; acc[n] = fmaf(v, v, acc[n]); }
        }
        int lane = t & 31, wid = t >> 5;            // 7 full warps
        #pragma unroll
        for (int n = 0; n < CELLS; n++) {
            float r = acc[n];
            #pragma unroll
            for (int o = 16; o; o >>= 1) r += __shfl_down_sync(0xffffffffu, r, o);
            if (lane == 0) sw[n][wid] = r;
        }
        __syncthreads();
        if (t < CELLS) {
            float ssum = 0.f;
            #pragma unroll
            for (int w = 0; w < 7; w++) ssum += sw[t][w];
            simp[t] = sqrtf(ssum);
        }
        __syncthreads();
        if (t < CELLS) {
            float mn = simp[0], mx = simp[0];
            #pragma unroll
            for (int n = 1; n < CELLS; n++) { mn = fminf(mn, simp[n]); mx = fmaxf(mx, simp[n]); }
            float imp01 = (simp[t] - mn) / (mx - mn + 1e-8f);
            float th   = 1.f / (1.f + expf(-logit_th[NUM_LEVELS - 1]));
            float hard = (imp01 >= th) ? 1.f : 0.f;
            float soft = 1.f / (1.f + expf(-(imp01 - th) * 10.f));
            float mask = fmaxf((hard - soft) + soft, 0.f);
            g_mask[b*CELLS + t] = mask;
            float keep = (mask > 0.5f) ? 1.f : 0.f;
            out_keep[b*CELLS + t] = keep;
            int r = t >> 2, cx = t & 3;
            ((float4*)out_coords)[b*CELLS + t] =
                make_float4((cx + 0.5f)*0.25f*keep, (r + 0.5f)*0.25f*keep,
                            0.25f*keep, 0.25f*keep);
        }
        __threadfence();
        __syncthreads();
        if (t == 0) atomicAdd(&g_flag[b], 1u);
    }

    // ---- Phase 3: spin until mask ready (epoch read predates any add) -----
    if (t == 0) {
        while (*((volatile unsigned*)&g_flag[b]) == s_epoch) __nanosleep(64);
        __threadfence();
    }
    __syncthreads();
    if (t < CELLS) s_m[t] = __ldcg(&g_mask[b*CELLS + t]);
    __syncthreads();

    // ---- Phase 4: sparse multiply, re-reading our own (L2-hot) slab -------
    int col4 = t % 56;                 // constant per thread
    float wx[4]; int jxA[4];
    #pragma unroll
    for (int i = 0; i < 4; i++) {
        float tx = fminf(fmaxf((col4*4 + i + 0.5f)*(1.f/56.f) - 0.5f, 0.f), 3.f);
        int jx = min((int)tx, 2);
        jxA[i] = jx; wx[i] = tx - (float)jx;
    }
    int rbase = t / 56;                // 0..3
    #pragma unroll
    for (int s = 0; s < 2; s++) {
        size_t base4 = ((size_t)(b*CC + c)*HH + gh*112 + s*56) * 56;
        int y0 = gh*112 + s*56 + rbase;
        #pragma unroll
        for (int j = 0; j < 14; j++) {
            int y = y0 + j*4;
            float ty = fminf(fmaxf((y + 0.5f)*(1.f/56.f) - 0.5f, 0.f), 3.f);
            int jy = min((int)ty, 2);
            float fy = ty - (float)jy;
            float r0 = s_m[jy*4+0] + (s_m[jy*4+4] - s_m[jy*4+0])*fy;
            float r1 = s_m[jy*4+1] + (s_m[jy*4+5] - s_m[jy*4+1])*fy;
            float r2 = s_m[jy*4+2] + (s_m[jy*4+6] - s_m[jy*4+2])*fy;
            float r3 = s_m[jy*4+3] + (s_m[jy*4+7] - s_m[jy*4+3])*fy;
            float mk[4];
            #pragma unroll
            for (int i = 0; i < 4; i++) {
                float a  = (jxA[i] == 0) ? r0 : (jxA[i] == 1) ? r1 : r2;
                float cc2= (jxA[i] == 0) ? r1 : (jxA[i] == 1) ? r2 : r3;
                mk[i] = a + (cc2 - a)*wx[i];
            }
            size_t idx = base4 + t + j*224;
            float4 v = __ldcs(&x4[idx]);             // L2 hit + demote
            __stcs(&o4[idx], make_float4(v.x*mk[0], v.y*mk[1], v.z*mk[2], v.w*mk[3]));
        }
    }
}

// ---------------------------------------------------------------------------
// LayerNorm + Linear over coarse cells, gated by keep (unchanged).
// ---------------------------------------------------------------------------
__global__ void k_proj(const float* __restrict__ gamma, const float* __restrict__ beta,
                       const float* __restrict__ wproj, const float* __restrict__ bproj,
                       float* __restrict__ out_feats) {
    int bn = blockIdx.x;             // b*16 + n
    int b = bn >> 4, n = bn & 15;
    int t = threadIdx.x;
    __shared__ float sf[256];
    __shared__ float sred[8];

    float f = g_coarse[((size_t)b*CC + t)*CELLS + n];
    int lane = t & 31, wid = t >> 5;

    float s = f;
    #pragma unroll
    for (int o = 16; o; o >>= 1) s += __shfl_down_sync(0xffffffffu, s, o);
    if (lane == 0) sred[wid] = s;
    __syncthreads();
    float mean = 0.f;
    #pragma unroll
    for (int w = 0; w < 8; w++) mean += sred[w];
    mean *= (1.f/256.f);
    __syncthreads();

    float d = f - mean;
    s = d*d;
    #pragma unroll
    for (int o = 16; o; o >>= 1) s += __shfl_down_sync(0xffffffffu, s, o);
    if (lane == 0) sred[wid] = s;
    __syncthreads();
    float var = 0.f;
    #pragma unroll
    for (int w = 0; w < 8; w++) var += sred[w];
    var *= (1.f/256.f);

    sf[t] = d * rsqrtf(var + 1e-5f) * gamma[t] + beta[t];
    __syncthreads();

    float acc = bproj[t];
    #pragma unroll 8
    for (int c = 0; c < 256; c++) acc = fmaf(sf[c], wproj[c*256 + t], acc);
    float keep = (g_mask[bn] > 0.5f) ? 1.f : 0.f;
    out_feats[(size_t)bn*256 + t] = acc * keep;
}

// ---------------------------------------------------------------------------
// Single stream, 9 graph nodes total.
// ---------------------------------------------------------------------------
extern "C" void kernel_launch(void* const* d_in, const int* in_sizes, int n_in,
                              void* d_out, int out_size) {
    const float* x     = (const float*)d_in[0];
    const float* logit = (const float*)d_in[1];
    const float* gamma = (const float*)d_in[2];
    const float* beta  = (const float*)d_in[3];
    const float* wproj = (const float*)d_in[4];
    const float* bproj = (const float*)d_in[5];

    float* out        = (float*)d_out;
    float* out_sparse = out;
    float* out_feats  = out + (size_t)BB*CC*HW;
    float* out_coords = out_feats + BB*CELLS*256;
    float* out_keep   = out_coords + BB*CELLS*4;

    for (int b = 0; b < BB; b++)
        k_fused<<<GRID_PER_B, 224>>>(x, (float4*)out_sparse, logit,
                                     out_keep, out_coords, b);
    k_proj<<<BB*CELLS, 256>>>(gamma, beta, wproj, bproj, out_feats);
}

// round 15
// speedup vs baseline: 1.4078x; 1.1707x over previous
#include <cuda_runtime.h>
#include <math.h>
#include <float.h>

#define BB 8
#define CC 256
#define HH 224
#define WW 224
#define CELLS 16
#define HW (HH*WW)
#define NUM_LEVELS 3
#define GRID_PER_B 256          // one channel per block

// scratch (no allocations allowed)
__device__ float    g_coarse[BB*CC*CELLS];  // [b][c][cell]
__device__ float    g_mask[BB*CELLS];
__device__ unsigned g_counter[BB];          // monotonic across replays
__device__ unsigned g_flag[BB];             // monotonic epoch per batch

// ---------------------------------------------------------------------------
// Fused per-batch kernel, one channel per block (224 threads).
// Thread t: col4 = t%56 (fixed float4 column), row0 = t/56; rows r = row0+4j.
// pool (read x once) -> last-block mask -> spin -> sparse (re-read own
// channel, L2-hot; ~200KB reuse distance).
// ---------------------------------------------------------------------------
__global__ void __launch_bounds__(224, 4)
k_fused(const float* __restrict__ x, float4* __restrict__ o4,
        const float* __restrict__ logit_th,
        float* __restrict__ out_keep, float* __restrict__ out_coords, int b)
{
    const float4* x4 = (const float4*)x;
    int c = blockIdx.x;
    int t = threadIdx.x;            // 0..223
    int col4 = t % 56, row0 = t / 56;
    size_t cb4 = (size_t)(b*CC + c) * (HH*56);   // channel base in float4

    __shared__ unsigned s_epoch;
    __shared__ float    scell[4*224];            // [gy][t]
    __shared__ float    sw[CELLS][7];
    __shared__ float    simp[CELLS];
    __shared__ float    s_m[CELLS];
    __shared__ int      s_last;

    if (t == 0) s_epoch = *((volatile unsigned*)&g_flag[b]);

    // ---- Phase 1: pool. j = 0..55, row r = row0+4j, gy = j/14 (const when
    // fully unrolled). 8 front-batched float4 loads per wave. ----------------
    float cm0 = -FLT_MAX, cm1 = -FLT_MAX, cm2 = -FLT_MAX, cm3 = -FLT_MAX;
    #pragma unroll
    for (int jo = 0; jo < 56; jo += 8) {
        float4 v[8];
        #pragma unroll
        for (int k = 0; k < 8; k++)
            v[k] = __ldg(&x4[cb4 + (size_t)(row0 + 4*(jo + k))*56 + col4]);
        #pragma unroll
        for (int k = 0; k < 8; k++) {
            float m = fmaxf(fmaxf(v[k].x, v[k].y), fmaxf(v[k].z, v[k].w));
            int gy = (jo + k) / 14;              // compile-time constant
            if (gy == 0)      cm0 = fmaxf(cm0, m);
            else if (gy == 1) cm1 = fmaxf(cm1, m);
            else if (gy == 2) cm2 = fmaxf(cm2, m);
            else              cm3 = fmaxf(cm3, m);
        }
    }
    scell[0*224 + t] = cm0; scell[1*224 + t] = cm1;
    scell[2*224 + t] = cm2; scell[3*224 + t] = cm3;
    __syncthreads();
    if (t < CELLS) {                             // t: gy = t>>2, gx = t&3
        int gy = t >> 2, gx = t & 3;
        float m = -FLT_MAX;
        #pragma unroll
        for (int r0 = 0; r0 < 4; r0++)
            #pragma unroll
            for (int q = 0; q < 14; q++)
                m = fmaxf(m, scell[gy*224 + r0*56 + gx*14 + q]);
        g_coarse[((size_t)(b*CC + c))*CELLS + t] = m;
    }
    __syncthreads();

    __threadfence();
    if (t == 0) {
        unsigned old = atomicAdd(&g_counter[b], 1u);
        s_last = ((old & (GRID_PER_B - 1u)) == GRID_PER_B - 1u) ? 1 : 0;
    }
    __syncthreads();

    // ---- Phase 2: last block -> importance -> mask -> keep/coords ---------
    if (s_last) {
        __threadfence();
        float acc[CELLS];
        #pragma unroll
        for (int n = 0; n < CELLS; n++) acc[n] = 0.f;
        for (int ch = t; ch < CC; ch += 224) {
            const float* row = g_coarse + ((size_t)b*CC + ch)*CELLS;
            #pragma unroll
            for (int n = 0; n < CELLS; n++) { float v = row[n]; acc[n] = fmaf(v, v, acc[n]); }
        }
        int lane = t & 31, wid = t >> 5;         // 7 full warps
        #pragma unroll
        for (int n = 0; n < CELLS; n++) {
            float r = acc[n];
            #pragma unroll
            for (int o = 16; o; o >>= 1) r += __shfl_down_sync(0xffffffffu, r, o);
            if (lane == 0) sw[n][wid] = r;
        }
        __syncthreads();
        if (t < CELLS) {
            float ssum = 0.f;
            #pragma unroll
            for (int w = 0; w < 7; w++) ssum += sw[t][w];
            simp[t] = sqrtf(ssum);
        }
        __syncthreads();
        if (t < CELLS) {
            float mn = simp[0], mx = simp[0];
            #pragma unroll
            for (int n = 1; n < CELLS; n++) { mn = fminf(mn, simp[n]); mx = fmaxf(mx, simp[n]); }
            float imp01 = (simp[t] - mn) / (mx - mn + 1e-8f);
            float th   = 1.f / (1.f + expf(-logit_th[NUM_LEVELS - 1]));
            float hard = (imp01 >= th) ? 1.f : 0.f;
            float soft = 1.f / (1.f + expf(-(imp01 - th) * 10.f));
            float mask = fmaxf((hard - soft) + soft, 0.f);
            g_mask[b*CELLS + t] = mask;
            float keep = (mask > 0.5f) ? 1.f : 0.f;
            out_keep[b*CELLS + t] = keep;
            int r = t >> 2, cx = t & 3;
            ((float4*)out_coords)[b*CELLS + t] =
                make_float4((cx + 0.5f)*0.25f*keep, (r + 0.5f)*0.25f*keep,
                            0.25f*keep, 0.25f*keep);
        }
        __threadfence();
        __syncthreads();
        if (t == 0) atomicAdd(&g_flag[b], 1u);
    }

    // ---- Phase 3: spin until mask ready -----------------------------------
    if (t == 0) {
        while (*((volatile unsigned*)&g_flag[b]) == s_epoch) __nanosleep(64);
        __threadfence();
    }
    __syncthreads();
    if (t < CELLS) s_m[t] = __ldcg(&g_mask[b*CELLS + t]);
    __syncthreads();

    // ---- Phase 4: sparse multiply over own channel (L2-hot) ---------------
    float wx[4]; int jxA[4];
    #pragma unroll
    for (int i = 0; i < 4; i++) {
        float tx = fminf(fmaxf((col4*4 + i + 0.5f)*(1.f/56.f) - 0.5f, 0.f), 3.f);
        int jx = min((int)tx, 2);
        jxA[i] = jx; wx[i] = tx - (float)jx;
    }
    #pragma unroll
    for (int jo = 0; jo < 56; jo += 8) {
        float4 v[8];
        #pragma unroll
        for (int k = 0; k < 8; k++)
            v[k] = __ldcs(&x4[cb4 + (size_t)(row0 + 4*(jo + k))*56 + col4]);
        #pragma unroll
        for (int k = 0; k < 8; k++) {
            int y = row0 + 4*(jo + k);
            float ty = fminf(fmaxf((y + 0.5f)*(1.f/56.f) - 0.5f, 0.f), 3.f);
            int jy = min((int)ty, 2);
            float fy = ty - (float)jy;
            float r0 = s_m[jy*4+0] + (s_m[jy*4+4] - s_m[jy*4+0])*fy;
            float r1 = s_m[jy*4+1] + (s_m[jy*4+5] - s_m[jy*4+1])*fy;
            float r2 = s_m[jy*4+2] + (s_m[jy*4+6] - s_m[jy*4+2])*fy;
            float r3 = s_m[jy*4+3] + (s_m[jy*4+7] - s_m[jy*4+3])*fy;
            float mk[4];
            #pragma unroll
            for (int i = 0; i < 4; i++) {
                float a  = (jxA[i] == 0) ? r0 : (jxA[i] == 1) ? r1 : r2;
                float c2 = (jxA[i] == 0) ? r1 : (jxA[i] == 1) ? r2 : r3;
                mk[i] = a + (c2 - a)*wx[i];
            }
            size_t idx = cb4 + (size_t)y*56 + col4;
            __stcs(&o4[idx], make_float4(v[k].x*mk[0], v[k].y*mk[1],
                                         v[k].z*mk[2], v[k].w*mk[3]));
        }
    }
}

// ---------------------------------------------------------------------------
// LayerNorm + Linear over coarse cells, gated by keep.
// ---------------------------------------------------------------------------
__global__ void k_proj(const float* __restrict__ gamma, const float* __restrict__ beta,
                       const float* __restrict__ wproj, const float* __restrict__ bproj,
                       float* __restrict__ out_feats) {
    int bn = blockIdx.x;             // b*16 + n
    int b = bn >> 4, n = bn & 15;
    int t = threadIdx.x;
    __shared__ float sf[256];
    __shared__ float sred[8];

    float f = g_coarse[((size_t)b*CC + t)*CELLS + n];
    int lane = t & 31, wid = t >> 5;

    float s = f;
    #pragma unroll
    for (int o = 16; o; o >>= 1) s += __shfl_down_sync(0xffffffffu, s, o);
    if (lane == 0) sred[wid] = s;
    __syncthreads();
    float mean = 0.f;
    #pragma unroll
    for (int w = 0; w < 8; w++) mean += sred[w];
    mean *= (1.f/256.f);
    __syncthreads();

    float d = f - mean;
    s = d*d;
    #pragma unroll
    for (int o = 16; o; o >>= 1) s += __shfl_down_sync(0xffffffffu, s, o);
    if (lane == 0) sred[wid] = s;
    __syncthreads();
    float var = 0.f;
    #pragma unroll
    for (int w = 0; w < 8; w++) var += sred[w];
    var *= (1.f/256.f);

    sf[t] = d * rsqrtf(var + 1e-5f) * gamma[t] + beta[t];
    __syncthreads();

    float acc = bproj[t];
    #pragma unroll 8
    for (int c = 0; c < 256; c++) acc = fmaf(sf[c], wproj[c*256 + t], acc);
    float keep = (g_mask[bn] > 0.5f) ? 1.f : 0.f;
    out_feats[(size_t)bn*256 + t] = acc * keep;
}

// ---------------------------------------------------------------------------
// Two-stream ping-pong: batch b on stream (b&1). Cohort = 256 blocks, two
// cohorts co-resident (592 slots) -> pool(b+1) DRAM reads overlap sparse(b)
// L2 reads + DRAM writes. Older kernel always fully resident -> no deadlock.
// ---------------------------------------------------------------------------
extern "C" void kernel_launch(void* const* d_in, const int* in_sizes, int n_in,
                              void* d_out, int out_size) {
    const float* x     = (const float*)d_in[0];
    const float* logit = (const float*)d_in[1];
    const float* gamma = (const float*)d_in[2];
    const float* beta  = (const float*)d_in[3];
    const float* wproj = (const float*)d_in[4];
    const float* bproj = (const float*)d_in[5];

    float* out        = (float*)d_out;
    float* out_sparse = out;
    float* out_feats  = out + (size_t)BB*CC*HW;
    float* out_coords = out_feats + BB*CELLS*256;
    float* out_keep   = out_coords + BB*CELLS*4;

    static cudaStream_t s1 = nullptr;
    static cudaEvent_t evRoot = nullptr, evJ = nullptr;
    if (s1 == nullptr) {
        cudaStreamCreateWithFlags(&s1, cudaStreamNonBlocking);
        cudaEventCreateWithFlags(&evRoot, cudaEventDisableTiming);
        cudaEventCreateWithFlags(&evJ, cudaEventDisableTiming);
    }

    cudaEventRecord(evRoot, 0);
    cudaStreamWaitEvent(s1, evRoot, 0);
    for (int b = 0; b < BB; b++) {
        cudaStream_t s = (b & 1) ? s1 : (cudaStream_t)0;
        k_fused<<<GRID_PER_B, 224, 0, s>>>(x, (float4*)out_sparse, logit,
                                           out_keep, out_coords, b);
    }
    cudaEventRecord(evJ, s1);
    cudaStreamWaitEvent(0, evJ, 0);
    k_proj<<<BB*CELLS, 256>>>(gamma, beta, wproj, bproj, out_feats);
}